// round 6
// baseline (speedup 1.0000x reference)
#include <cuda_runtime.h>

#define BSZ   4
#define CH    128
#define HID   256
#define OUTD  64
#define EPSV  1e-5f
#define ALLM  0xffffffffu
#define RPAD  260              // padded row stride (floats) = 65 float4
#define W2PAD 65               // float4 stride per w2 row in smem

// ---------------------------------------------------------------------------
// One block per pyramid level, 1024 threads, zero inter-block traffic.
//   phase1: (j = t>>2, q = t&3): 32-ch partial dot x 4 batches, shfl-reduce,
//           BN (batch stats thread-local after reduce) + ReLU -> r_s (smem).
//   w2 level slice staged to smem at start (conflict-free padded layout).
//   phase2: 256 threads, thread = (b,o), full 256-dot from smem.
// ---------------------------------------------------------------------------
__global__ __launch_bounds__(1024, 1)
void proj_fused_kernel(const float* __restrict__ x0,
                       const float* __restrict__ x1,
                       const float* __restrict__ x2,
                       const float* __restrict__ x3,
                       const float* __restrict__ x4,
                       const int*   __restrict__ p,
                       const float* __restrict__ w1,
                       const float* __restrict__ b1,
                       const float* __restrict__ gamma,
                       const float* __restrict__ beta,
                       const float* __restrict__ w2,
                       const float* __restrict__ b2,
                       float*       __restrict__ out)
{
    const int k = blockIdx.x;          // level 0..4
    const int t = threadIdx.x;         // 0..1023

    __shared__ float  f_s[BSZ][CH];            // gathered features
    __shared__ float  r_s[BSZ * RPAD];         // post-ReLU hidden (padded rows)
    __shared__ float4 w2_s[OUTD * W2PAD];      // staged W2 level slice (padded)

    const int j = t >> 2;              // hidden unit 0..255
    const int q = t & 3;               // channel quarter (32 ch)

    // ---- stage W2 level slice into smem (independent of everything) ----
    {
        const float4* w2g = (const float4*)(w2 + (long long)k * OUTD * HID);
        #pragma unroll
        for (int i = 0; i < 4; ++i) {
            const int g  = t + i * 1024;       // float4 index 0..4095
            const int o  = g >> 6;
            const int h4 = g & 63;
            w2_s[o * W2PAD + h4] = w2g[g];
        }
    }

    // ---- prefetch w1 + BN params ----
    const float4* wrow = (const float4*)(w1 + ((long long)k * HID + j) * CH);
    float4 wv[8];
    #pragma unroll
    for (int i = 0; i < 8; ++i)
        wv[i] = wrow[q + 4 * i];

    const float bias = b1[k * HID + j];
    const float gam  = gamma[k * HID + j];
    const float bet  = beta[k * HID + j];

    // ---- gather 512 scattered floats (threads 0..511, one each) ----
    const float* xs;
    switch (k) {
        case 0: xs = x0; break;
        case 1: xs = x1; break;
        case 2: xs = x2; break;
        case 3: xs = x3; break;
        default: xs = x4; break;
    }
    const int shift = k + 1;
    const int side  = 128 >> shift;

    if (t < BSZ * CH) {
        const int b = t >> 7;
        const int c = t & (CH - 1);
        const int q0 = p[b * 3 + 0] >> shift;
        const int q1 = p[b * 3 + 1] >> shift;
        const int q2 = p[b * 3 + 2] >> shift;
        const long long idx =
            ((((long long)(b * CH + c) * side + q0) * side + q1) * side + q2);
        f_s[b][c] = xs[idx];
    }
    __syncthreads();

    // ---- phase1: 8 interleaved float4 x 4 batches ----
    const float4* f0 = (const float4*)f_s[0];
    const float4* f1 = (const float4*)f_s[1];
    const float4* f2 = (const float4*)f_s[2];
    const float4* f3 = (const float4*)f_s[3];

    float a0 = 0.f, a1 = 0.f, a2 = 0.f, a3 = 0.f;
    #pragma unroll
    for (int i = 0; i < 8; ++i) {
        const int fi = q + 4 * i;
        const float4 w = wv[i];
        float4 v;
        v = f0[fi]; a0 += v.x*w.x + v.y*w.y + v.z*w.z + v.w*w.w;
        v = f1[fi]; a1 += v.x*w.x + v.y*w.y + v.z*w.z + v.w*w.w;
        v = f2[fi]; a2 += v.x*w.x + v.y*w.y + v.z*w.z + v.w*w.w;
        v = f3[fi]; a3 += v.x*w.x + v.y*w.y + v.z*w.z + v.w*w.w;
    }
    // reduce over the 4 q-lanes
    #pragma unroll
    for (int m = 1; m < 4; m <<= 1) {
        a0 += __shfl_xor_sync(ALLM, a0, m);
        a1 += __shfl_xor_sync(ALLM, a1, m);
        a2 += __shfl_xor_sync(ALLM, a2, m);
        a3 += __shfl_xor_sync(ALLM, a3, m);
    }

    // ---- BN + ReLU; lane q writes batch b=q ----
    a0 += bias; a1 += bias; a2 += bias; a3 += bias;
    const float mean = 0.25f * (a0 + a1 + a2 + a3);
    const float d0 = a0 - mean, d1 = a1 - mean, d2 = a2 - mean, d3 = a3 - mean;
    const float var = 0.25f * (d0*d0 + d1*d1 + d2*d2 + d3*d3);
    const float scl = gam * rsqrtf(var + EPSV);

    const float d = (q == 0) ? d0 : (q == 1) ? d1 : (q == 2) ? d2 : d3;
    r_s[q * RPAD + j] = fmaxf(d * scl + bet, 0.f);
    __syncthreads();

    // ---- phase2: 256 threads, thread = (b = t>>6, o = t&63) ----
    if (t < BSZ * OUTD) {
        const int b = t >> 6;
        const int o = t & (OUTD - 1);

        const float4* rrow = (const float4*)(r_s + b * RPAD);  // RPAD%4==0
        const float4* wrow2 = w2_s + o * W2PAD;

        float cx = 0.f, cy = 0.f, cz = 0.f, cw = 0.f;
        #pragma unroll
        for (int i = 0; i < 64; ++i) {
            const float4 w = wrow2[i];
            const float4 r = rrow[i];
            cx += r.x * w.x;
            cy += r.y * w.y;
            cz += r.z * w.z;
            cw += r.w * w.w;
        }
        out[k * (BSZ * OUTD) + t] = (cx + cy) + (cz + cw) + b2[k * OUTD + o];
    }
}

extern "C" void kernel_launch(void* const* d_in, const int* in_sizes, int n_in,
                              void* d_out, int out_size)
{
    (void)in_sizes; (void)n_in; (void)out_size;
    const float* x0    = (const float*)d_in[0];
    const float* x1    = (const float*)d_in[1];
    const float* x2    = (const float*)d_in[2];
    const float* x3    = (const float*)d_in[3];
    const float* x4    = (const float*)d_in[4];
    const int*   p     = (const int*)  d_in[5];
    const float* w1    = (const float*)d_in[6];
    const float* b1    = (const float*)d_in[7];
    const float* gamma = (const float*)d_in[8];
    const float* beta  = (const float*)d_in[9];
    const float* w2    = (const float*)d_in[10];
    const float* b2v   = (const float*)d_in[11];
    float* out = (float*)d_out;

    proj_fused_kernel<<<5, 1024>>>(x0, x1, x2, x3, x4, p,
                                   w1, b1, gamma, beta, w2, b2v, out);
}